// round 14
// baseline (speedup 1.0000x reference)
#include <cuda_runtime.h>

// ListMLE: B=8192 rows, N=4096, labels int32.
//   result = [ Σ_j log(S_j) - Σ x ] / (B*N),  S_j = cumsum_j exp(x[label[j]])
// Locked structure (rounds 8-13): 1 row/block, 256 thr, regs<=32, 8 blocks/SM.
// Round-14: stage the fp32 row with ONE cp.async.bulk (16 KB, mbarrier
// completion) instead of 1024 per-thread LDGSTS -> staging leaves the SM
// issue/LSU path entirely; first half of the label LDGs issue while the bulk
// copy is in flight (overlaps the two DRAM round-trips). Logs fused per 4.
// Fused deterministic finalize via fence+counter (fp64 fixed-order sum).

#define B_ROWS  8192
#define N_COLS  4096
#define THREADS 256
#define CHUNK   (N_COLS / THREADS)   // 16
#define NWARPS  (THREADS / 32)       // 8
#define LN2F    0.6931471805599453f

__device__ float        g_partial[B_ROWS];
__device__ unsigned int g_count = 0;

__global__ __launch_bounds__(THREADS, 8)
void listmle_main(const float* __restrict__ outputs,
                  const int* __restrict__ labels,
                  float* __restrict__ out) {
    __shared__ __align__(16) float x_s[N_COLS];   // 16 KB raw fp32 row
    __shared__ unsigned long long  mbar;
    __shared__ float  warp_tot[NWARPS];
    __shared__ float  red_s[NWARPS];
    __shared__ double sd[NWARPS];
    __shared__ bool   is_last;

    const int row  = blockIdx.x;
    const int t    = threadIdx.x;
    const int lane = t & 31;
    const int wid  = t >> 5;
    const unsigned full = 0xFFFFFFFFu;

    const int4* lsrc = (const int4*)(labels + (size_t)row * N_COLS);
    const unsigned mb = (unsigned)__cvta_generic_to_shared(&mbar);

    // ---- init mbarrier, publish, then launch bulk copy from thread 0 ----
    if (t == 0)
        asm volatile("mbarrier.init.shared.b64 [%0], 1;" :: "r"(mb) : "memory");
    __syncthreads();
    if (t == 0) {
        asm volatile("mbarrier.arrive.expect_tx.shared.b64 _, [%0], %1;"
                     :: "r"(mb), "r"(N_COLS * 4) : "memory");
        const unsigned sdst = (unsigned)__cvta_generic_to_shared(x_s);
        asm volatile(
            "cp.async.bulk.shared::cta.global.mbarrier::complete_tx::bytes "
            "[%0], [%1], %2, [%3];"
            :: "r"(sdst), "l"(outputs + (size_t)row * N_COLS),
               "r"(N_COLS * 4), "r"(mb) : "memory");
    }

    // ---- overlap: first half of label loads while the bulk copy flies ----
    int4 l0 = lsrc[4 * t + 0];
    int4 l1 = lsrc[4 * t + 1];

    // ---- wait for the row (acquire orders async writes before our LDS) ----
    {
        unsigned done;
        asm volatile(
            "{\n\t.reg .pred p;\n\t"
            "mbarrier.try_wait.parity.acquire.cta.shared::cta.b64 p, [%1], 0;\n\t"
            "selp.b32 %0, 1, 0, p;\n\t}"
            : "=r"(done) : "r"(mb) : "memory");
        if (!done) {
            asm volatile(
                "{\n\t.reg .pred P1;\n\t"
                "W%=:\n\t"
                "mbarrier.try_wait.parity.acquire.cta.shared::cta.b64 P1, [%0], 0, 0x989680;\n\t"
                "@P1 bra.uni D%=;\n\t"
                "bra.uni W%=;\n\t"
                "D%=:\n\t}"
                :: "r"(mb) : "memory");
        }
    }

    // ---- pass 1: gather x, sum x, exp -> ev ----
    float ev[CHUNK];
    float acc_x;
    {
        float x0 = x_s[l0.x], x1 = x_s[l0.y], x2 = x_s[l0.z], x3 = x_s[l0.w];
        float x4 = x_s[l1.x], x5 = x_s[l1.y], x6 = x_s[l1.z], x7 = x_s[l1.w];
        acc_x = ((x0 + x1) + (x2 + x3)) + ((x4 + x5) + (x6 + x7));
        ev[0] = __expf(x0); ev[1] = __expf(x1);
        ev[2] = __expf(x2); ev[3] = __expf(x3);
        ev[4] = __expf(x4); ev[5] = __expf(x5);
        ev[6] = __expf(x6); ev[7] = __expf(x7);
    }
    {
        int4 l2 = lsrc[4 * t + 2];
        int4 l3 = lsrc[4 * t + 3];
        float x0 = x_s[l2.x], x1 = x_s[l2.y], x2 = x_s[l2.z], x3 = x_s[l2.w];
        float x4 = x_s[l3.x], x5 = x_s[l3.y], x6 = x_s[l3.z], x7 = x_s[l3.w];
        acc_x += ((x0 + x1) + (x2 + x3)) + ((x4 + x5) + (x6 + x7));
        ev[ 8] = __expf(x0); ev[ 9] = __expf(x1);
        ev[10] = __expf(x2); ev[11] = __expf(x3);
        ev[12] = __expf(x4); ev[13] = __expf(x5);
        ev[14] = __expf(x6); ev[15] = __expf(x7);
    }

    float tsum = 0.0f;
    #pragma unroll
    for (int i = 0; i < CHUNK; i += 4)
        tsum += ((ev[i] + ev[i + 1]) + (ev[i + 2] + ev[i + 3]));

    // ---- block exclusive add-scan over thread sums ----
    float incl = tsum;
    #pragma unroll
    for (int off = 1; off < 32; off <<= 1) {
        float v = __shfl_up_sync(full, incl, off);
        if (lane >= off) incl += v;
    }
    if (lane == 31) warp_tot[wid] = incl;
    __syncthreads();

    float woff = 0.0f;                    // wid uniform within warp
    #pragma unroll
    for (int w = 0; w < NWARPS; w++)
        if (w < wid) woff += warp_tot[w];

    float excl = __shfl_up_sync(full, incl, 1);
    if (lane == 0) excl = 0.0f;
    float S = woff + excl;                // exclusive prefix of exp-sums

    // ---- pass 2: running cumsum; fused log per group of 4 ----
    float acc2 = 0.0f;
    #pragma unroll
    for (int i = 0; i < CHUNK; i += 4) {
        float s0 = S + ev[i];
        float s1 = s0 + ev[i + 1];
        float s2 = s1 + ev[i + 2];
        float s3 = s2 + ev[i + 3];
        S = s3;
        float p = (s0 * s1) * (s2 * s3);  // < ~2.4e15, fp32-safe
        acc2 += __log2f(p);
    }
    float acc = acc2 * LN2F - acc_x;

    // ---- block reduce -> per-row partial ----
    #pragma unroll
    for (int off = 16; off > 0; off >>= 1)
        acc += __shfl_down_sync(full, acc, off);
    if (lane == 0) red_s[wid] = acc;
    __syncthreads();
    if (t == 0) {
        float bs = 0.0f;
        #pragma unroll
        for (int w = 0; w < NWARPS; w++) bs += red_s[w];
        g_partial[row] = bs;
        __threadfence();
        unsigned old = atomicAdd(&g_count, 1u);
        is_last = (old == (unsigned)(gridDim.x - 1));
    }
    __syncthreads();

    // ---- last block: deterministic fp64 final reduction ----
    if (is_last) {
        double a = 0.0;
        for (int i = t; i < B_ROWS; i += THREADS)
            a += (double)g_partial[i];
        #pragma unroll
        for (int off = 16; off > 0; off >>= 1)
            a += __shfl_down_sync(full, a, off);
        if (lane == 0) sd[wid] = a;
        __syncthreads();
        if (t == 0) {
            double s = 0.0;
            #pragma unroll
            for (int w = 0; w < NWARPS; w++) s += sd[w];
            out[0] = (float)(s / ((double)B_ROWS * (double)N_COLS));
            g_count = 0;   // reset for next graph replay
        }
    }
}

extern "C" void kernel_launch(void* const* d_in, const int* in_sizes, int n_in,
                              void* d_out, int out_size) {
    const float* outputs = (const float*)d_in[0];
    const int*   labels  = (const int*)d_in[1];
    float*       out     = (float*)d_out;
    (void)in_sizes; (void)n_in; (void)out_size;

    listmle_main<<<B_ROWS, THREADS>>>(outputs, labels, out);
}

// round 15
// speedup vs baseline: 1.0406x; 1.0406x over previous
#include <cuda_runtime.h>

// ListMLE: B=8192 rows, N=4096, labels int32.
//   result = [ Σ_j log(S_j) - Σ x ] / (B*N),  S_j = cumsum_j exp(x[label[j]])
// Locked structure (rounds 8-14): 1 row/block, 256 thr, regs<=32, 8 blocks/SM,
// per-thread cp.async.cg staging (round-14 proved single-bulk-TMA is WORSE:
// later issue + mbarrier wait cost > LDGSTS issue cost). Round-15 delta vs the
// 50.8us round-13 kernel: first half of label LDGs issue BETWEEN cp.async
// commit and wait, overlapping the label DRAM round-trip with the row copy.
// Logs fused per 4 (prod of 4 prefix sums < 2.4e15, fp32-safe).
// Fused deterministic finalize via fence+counter (fp64 fixed-order sum).

#define B_ROWS  8192
#define N_COLS  4096
#define THREADS 256
#define CHUNK   (N_COLS / THREADS)   // 16
#define NWARPS  (THREADS / 32)       // 8
#define LN2F    0.6931471805599453f

__device__ float        g_partial[B_ROWS];
__device__ unsigned int g_count = 0;

__device__ __forceinline__ void cp16(unsigned dst, const void* src) {
    asm volatile("cp.async.cg.shared.global [%0], [%1], 16;" :: "r"(dst), "l"(src));
}

__global__ __launch_bounds__(THREADS, 8)
void listmle_main(const float* __restrict__ outputs,
                  const int* __restrict__ labels,
                  float* __restrict__ out) {
    __shared__ float  x_s[N_COLS];          // 16 KB: raw fp32 row
    __shared__ float  warp_tot[NWARPS];
    __shared__ float  red_s[NWARPS];
    __shared__ double sd[NWARPS];
    __shared__ bool   is_last;

    const int row  = blockIdx.x;
    const int t    = threadIdx.x;
    const int lane = t & 31;
    const int wid  = t >> 5;
    const unsigned full = 0xFFFFFFFFu;

    const int4* lsrc = (const int4*)(labels + (size_t)row * N_COLS);

    // ---- stage raw row via cp.async; overlap label LDGs with the copy ----
    {
        const char* src = (const char*)(outputs + (size_t)row * N_COLS);
        const unsigned sb = (unsigned)__cvta_generic_to_shared(x_s);
        #pragma unroll
        for (int k = 0; k < 4; k++) {
            unsigned off = (unsigned)(t + k * THREADS) * 16u;
            cp16(sb + off, src + off);
        }
        asm volatile("cp.async.commit_group;");
    }
    int4 l0 = lsrc[4 * t + 0];              // in flight under the row copy
    int4 l1 = lsrc[4 * t + 1];
    asm volatile("cp.async.wait_group 0;");
    __syncthreads();

    // ---- pass 1: gather x, sum x, exp -> ev (staggered label loads) ----
    float ev[CHUNK];
    float acc_x;
    {
        float x0 = x_s[l0.x], x1 = x_s[l0.y], x2 = x_s[l0.z], x3 = x_s[l0.w];
        float x4 = x_s[l1.x], x5 = x_s[l1.y], x6 = x_s[l1.z], x7 = x_s[l1.w];
        acc_x = ((x0 + x1) + (x2 + x3)) + ((x4 + x5) + (x6 + x7));
        ev[0] = __expf(x0); ev[1] = __expf(x1);
        ev[2] = __expf(x2); ev[3] = __expf(x3);
        ev[4] = __expf(x4); ev[5] = __expf(x5);
        ev[6] = __expf(x6); ev[7] = __expf(x7);
    }
    {
        int4 l2 = lsrc[4 * t + 2];
        int4 l3 = lsrc[4 * t + 3];
        float x0 = x_s[l2.x], x1 = x_s[l2.y], x2 = x_s[l2.z], x3 = x_s[l2.w];
        float x4 = x_s[l3.x], x5 = x_s[l3.y], x6 = x_s[l3.z], x7 = x_s[l3.w];
        acc_x += ((x0 + x1) + (x2 + x3)) + ((x4 + x5) + (x6 + x7));
        ev[ 8] = __expf(x0); ev[ 9] = __expf(x1);
        ev[10] = __expf(x2); ev[11] = __expf(x3);
        ev[12] = __expf(x4); ev[13] = __expf(x5);
        ev[14] = __expf(x6); ev[15] = __expf(x7);
    }

    float tsum = 0.0f;
    #pragma unroll
    for (int i = 0; i < CHUNK; i += 4)
        tsum += ((ev[i] + ev[i + 1]) + (ev[i + 2] + ev[i + 3]));

    // ---- block exclusive add-scan over thread sums ----
    float incl = tsum;
    #pragma unroll
    for (int off = 1; off < 32; off <<= 1) {
        float v = __shfl_up_sync(full, incl, off);
        if (lane >= off) incl += v;
    }
    if (lane == 31) warp_tot[wid] = incl;
    __syncthreads();

    float woff = 0.0f;                    // wid uniform within warp
    #pragma unroll
    for (int w = 0; w < NWARPS; w++)
        if (w < wid) woff += warp_tot[w];

    float excl = __shfl_up_sync(full, incl, 1);
    if (lane == 0) excl = 0.0f;
    float S = woff + excl;                // exclusive prefix of exp-sums

    // ---- pass 2: running cumsum; fused log per group of 4 ----
    float acc2 = 0.0f;
    #pragma unroll
    for (int i = 0; i < CHUNK; i += 4) {
        float s0 = S + ev[i];
        float s1 = s0 + ev[i + 1];
        float s2 = s1 + ev[i + 2];
        float s3 = s2 + ev[i + 3];
        S = s3;
        float p = (s0 * s1) * (s2 * s3);  // < ~2.4e15, fp32-safe
        acc2 += __log2f(p);
    }
    float acc = acc2 * LN2F - acc_x;

    // ---- block reduce -> per-row partial ----
    #pragma unroll
    for (int off = 16; off > 0; off >>= 1)
        acc += __shfl_down_sync(full, acc, off);
    if (lane == 0) red_s[wid] = acc;
    __syncthreads();
    if (t == 0) {
        float bs = 0.0f;
        #pragma unroll
        for (int w = 0; w < NWARPS; w++) bs += red_s[w];
        g_partial[row] = bs;
        __threadfence();
        unsigned old = atomicAdd(&g_count, 1u);
        is_last = (old == (unsigned)(gridDim.x - 1));
    }
    __syncthreads();

    // ---- last block: deterministic fp64 final reduction ----
    if (is_last) {
        double a = 0.0;
        for (int i = t; i < B_ROWS; i += THREADS)
            a += (double)g_partial[i];
        #pragma unroll
        for (int off = 16; off > 0; off >>= 1)
            a += __shfl_down_sync(full, a, off);
        if (lane == 0) sd[wid] = a;
        __syncthreads();
        if (t == 0) {
            double s = 0.0;
            #pragma unroll
            for (int w = 0; w < NWARPS; w++) s += sd[w];
            out[0] = (float)(s / ((double)B_ROWS * (double)N_COLS));
            g_count = 0;   // reset for next graph replay
        }
    }
}

extern "C" void kernel_launch(void* const* d_in, const int* in_sizes, int n_in,
                              void* d_out, int out_size) {
    const float* outputs = (const float*)d_in[0];
    const int*   labels  = (const int*)d_in[1];
    float*       out     = (float*)d_out;
    (void)in_sizes; (void)n_in; (void)out_size;

    listmle_main<<<B_ROWS, THREADS>>>(outputs, labels, out);
}

// round 16
// speedup vs baseline: 1.0748x; 1.0329x over previous
#include <cuda_runtime.h>

// ListMLE: B=8192 rows, N=4096, labels int32.
//   result = [ Σ_j log(S_j) - Σ x ] / (B*N),  S_j = cumsum_j exp(x[label[j]])
// Locked structure (rounds 8-15): 1 row/block, 256 thr, regs<=32, 8 blocks/SM,
// per-thread cp.async.cg staging of the raw fp32 row (best measured: 50.8us).
// Round-14 (bulk-TMA) and round-15 (label overlap) both regressed/neutral ->
// exact round-13 ordering restored. This round's only delta: the per-warp
// scan-offset loop is replaced by a 3-step shfl scan (+1 broadcast), saving
// ~17 issue slots/thread in the post-barrier shadow.
// Logs fused per 4 (prod of 4 prefix sums < 2.4e15, fp32-safe).
// Fused deterministic finalize via fence+counter (fp64 fixed-order sum).

#define B_ROWS  8192
#define N_COLS  4096
#define THREADS 256
#define CHUNK   (N_COLS / THREADS)   // 16
#define NWARPS  (THREADS / 32)       // 8
#define LN2F    0.6931471805599453f

__device__ float        g_partial[B_ROWS];
__device__ unsigned int g_count = 0;

__device__ __forceinline__ void cp16(unsigned dst, const void* src) {
    asm volatile("cp.async.cg.shared.global [%0], [%1], 16;" :: "r"(dst), "l"(src));
}

__global__ __launch_bounds__(THREADS, 8)
void listmle_main(const float* __restrict__ outputs,
                  const int* __restrict__ labels,
                  float* __restrict__ out) {
    __shared__ float  x_s[N_COLS];          // 16 KB: raw fp32 row
    __shared__ float  warp_tot[NWARPS];
    __shared__ float  red_s[NWARPS];
    __shared__ double sd[NWARPS];
    __shared__ bool   is_last;

    const int row  = blockIdx.x;
    const int t    = threadIdx.x;
    const int lane = t & 31;
    const int wid  = t >> 5;
    const unsigned full = 0xFFFFFFFFu;

    const int4* lsrc = (const int4*)(labels + (size_t)row * N_COLS);

    // ---- stage raw row via cp.async (register-free staging) ----
    {
        const char* src = (const char*)(outputs + (size_t)row * N_COLS);
        const unsigned sb = (unsigned)__cvta_generic_to_shared(x_s);
        #pragma unroll
        for (int k = 0; k < 4; k++) {
            unsigned off = (unsigned)(t + k * THREADS) * 16u;
            cp16(sb + off, src + off);
        }
        asm volatile("cp.async.commit_group;");
        asm volatile("cp.async.wait_group 0;");
    }
    __syncthreads();

    // ---- pass 1: gather x, sum x, exp -> ev (staggered label loads) ----
    float ev[CHUNK];
    float acc_x;
    {
        int4 l0 = lsrc[4 * t + 0];
        int4 l1 = lsrc[4 * t + 1];
        float x0 = x_s[l0.x], x1 = x_s[l0.y], x2 = x_s[l0.z], x3 = x_s[l0.w];
        float x4 = x_s[l1.x], x5 = x_s[l1.y], x6 = x_s[l1.z], x7 = x_s[l1.w];
        acc_x = ((x0 + x1) + (x2 + x3)) + ((x4 + x5) + (x6 + x7));
        ev[0] = __expf(x0); ev[1] = __expf(x1);
        ev[2] = __expf(x2); ev[3] = __expf(x3);
        ev[4] = __expf(x4); ev[5] = __expf(x5);
        ev[6] = __expf(x6); ev[7] = __expf(x7);
    }
    {
        int4 l2 = lsrc[4 * t + 2];
        int4 l3 = lsrc[4 * t + 3];
        float x0 = x_s[l2.x], x1 = x_s[l2.y], x2 = x_s[l2.z], x3 = x_s[l2.w];
        float x4 = x_s[l3.x], x5 = x_s[l3.y], x6 = x_s[l3.z], x7 = x_s[l3.w];
        acc_x += ((x0 + x1) + (x2 + x3)) + ((x4 + x5) + (x6 + x7));
        ev[ 8] = __expf(x0); ev[ 9] = __expf(x1);
        ev[10] = __expf(x2); ev[11] = __expf(x3);
        ev[12] = __expf(x4); ev[13] = __expf(x5);
        ev[14] = __expf(x6); ev[15] = __expf(x7);
    }

    float tsum = 0.0f;
    #pragma unroll
    for (int i = 0; i < CHUNK; i += 4)
        tsum += ((ev[i] + ev[i + 1]) + (ev[i + 2] + ev[i + 3]));

    // ---- block exclusive add-scan over thread sums ----
    float incl = tsum;
    #pragma unroll
    for (int off = 1; off < 32; off <<= 1) {
        float v = __shfl_up_sync(full, incl, off);
        if (lane >= off) incl += v;
    }
    if (lane == 31) warp_tot[wid] = incl;
    __syncthreads();

    // shfl-based warp-offset: lanes 0..7 scan warp_tot, broadcast wid-1
    float wv = (lane < NWARPS) ? warp_tot[lane] : 0.0f;
    #pragma unroll
    for (int off = 1; off < NWARPS; off <<= 1) {
        float v = __shfl_up_sync(full, wv, off);
        if (lane >= off) wv += v;
    }
    float wpick = __shfl_sync(full, wv, (wid == 0) ? 0 : (wid - 1));
    float woff  = (wid == 0) ? 0.0f : wpick;

    float excl = __shfl_up_sync(full, incl, 1);
    if (lane == 0) excl = 0.0f;
    float S = woff + excl;                // exclusive prefix of exp-sums

    // ---- pass 2: running cumsum; fused log per group of 4 ----
    float acc2 = 0.0f;
    #pragma unroll
    for (int i = 0; i < CHUNK; i += 4) {
        float s0 = S + ev[i];
        float s1 = s0 + ev[i + 1];
        float s2 = s1 + ev[i + 2];
        float s3 = s2 + ev[i + 3];
        S = s3;
        float p = (s0 * s1) * (s2 * s3);  // < ~2.4e15, fp32-safe
        acc2 += __log2f(p);
    }
    float acc = acc2 * LN2F - acc_x;

    // ---- block reduce -> per-row partial ----
    #pragma unroll
    for (int off = 16; off > 0; off >>= 1)
        acc += __shfl_down_sync(full, acc, off);
    if (lane == 0) red_s[wid] = acc;
    __syncthreads();
    if (t == 0) {
        float bs = 0.0f;
        #pragma unroll
        for (int w = 0; w < NWARPS; w++) bs += red_s[w];
        g_partial[row] = bs;
        __threadfence();
        unsigned old = atomicAdd(&g_count, 1u);
        is_last = (old == (unsigned)(gridDim.x - 1));
    }
    __syncthreads();

    // ---- last block: deterministic fp64 final reduction ----
    if (is_last) {
        double a = 0.0;
        for (int i = t; i < B_ROWS; i += THREADS)
            a += (double)g_partial[i];
        #pragma unroll
        for (int off = 16; off > 0; off >>= 1)
            a += __shfl_down_sync(full, a, off);
        if (lane == 0) sd[wid] = a;
        __syncthreads();
        if (t == 0) {
            double s = 0.0;
            #pragma unroll
            for (int w = 0; w < NWARPS; w++) s += sd[w];
            out[0] = (float)(s / ((double)B_ROWS * (double)N_COLS));
            g_count = 0;   // reset for next graph replay
        }
    }
}

extern "C" void kernel_launch(void* const* d_in, const int* in_sizes, int n_in,
                              void* d_out, int out_size) {
    const float* outputs = (const float*)d_in[0];
    const int*   labels  = (const int*)d_in[1];
    float*       out     = (float*)d_out;
    (void)in_sizes; (void)n_in; (void)out_size;

    listmle_main<<<B_ROWS, THREADS>>>(outputs, labels, out);
}